// round 10
// baseline (speedup 1.0000x reference)
#include <cuda_runtime.h>
#include <cuda_bf16.h>
#include <math.h>
#include <stdint.h>

#define BB 64
#define TT 2048
#define DD 128
#define UU 128
#define WPAD 136                        // padded bf16 row -> conflict-free frags
#define TM 64                           // tokens per tile
#define NTILE 32                        // tiles per batch
#define NT (BB * NTILE)                 // 2048 tiles
#define GRID 296                        // 148 SMs x 2 CTAs
#define TSTRIDE 132                     // 128 ctx + M + S + pad

__device__ float g_tile[NT * TSTRIDE];
__device__ unsigned int g_bdone[BB];    // per-batch tile counters (zero-init)

// ---- smem layout (bytes), total 109184 -> 2 CTAs/SM (218 KB < 227 KB) ----
#define S_BIAS 0                        // float[128]
#define S_V    512                      // float[128]
#define S_PART 1024                     // float[4][64]
#define S_SC   2048                     // float[64]
#define S_RED  2304                     // float[8]
#define S_FLAG 2368                     // int (pad to 2432)
#define S_CTX  2432                     // float[4][128]
#define S_CW   4480                     // float[32] combine weights
#define S_CIS  4608                     // float  (pad to 4736)
#define S_XHI  4736                     // bf16[64][WPAD] = 17408
#define S_XLO  22144
#define S_WHI  39552                    // bf16[128][WPAD] = 34816
#define S_WLO  74368
#define S_TOTAL 109184

__device__ __forceinline__ void mma16816(float* c, const uint32_t* a, const uint32_t* b) {
    asm volatile(
        "mma.sync.aligned.m16n8k16.row.col.f32.bf16.bf16.f32 "
        "{%0,%1,%2,%3}, {%4,%5,%6,%7}, {%8,%9}, {%0,%1,%2,%3};"
        : "+f"(c[0]), "+f"(c[1]), "+f"(c[2]), "+f"(c[3])
        : "r"(a[0]), "r"(a[1]), "r"(a[2]), "r"(a[3]), "r"(b[0]), "r"(b[1]));
}
__device__ __forceinline__ float tanh_ap(float x) {
    float r;
    asm("tanh.approx.f32 %0, %1;" : "=f"(r) : "f"(x));
    return r;
}
__device__ __forceinline__ void split2(float2 v, uint32_t& hi, uint32_t& lo) {
    __nv_bfloat162 h = __float22bfloat162_rn(v);
    float2 hf = __bfloat1622float2(h);
    __nv_bfloat162 l = __float22bfloat162_rn(make_float2(v.x - hf.x, v.y - hf.y));
    hi = *(uint32_t*)&h;
    lo = *(uint32_t*)&l;
}

__global__ void __launch_bounds__(256, 2) fused_kernel(const float* __restrict__ x,
                                                       const float* __restrict__ W1,
                                                       const float* __restrict__ W2,
                                                       const float* __restrict__ b1,
                                                       const float* __restrict__ b2,
                                                       const float* __restrict__ Vw,
                                                       float* __restrict__ out) {
    extern __shared__ __align__(16) char smem[];
    const int tid = threadIdx.x, wid = tid >> 5, lane = tid & 31;
    const int g = lane >> 2, q = lane & 3;
    const int wm = wid & 1, wn = wid >> 1;       // 2x4 warp grid: 32x32 out tiles

    // ---- one-time: bias/V ; Wsum -> transpose-split into WHI/WLO ----
    if (tid < 128) {
        ((float*)(smem + S_BIAS))[tid] = b1[tid] + b2[tid];
        ((float*)(smem + S_V))[tid] = Vw[tid];
    }
    {
        const int u = tid & 127;
        const int k0 = (tid >> 7) * 64;
#pragma unroll
        for (int k = k0; k < k0 + 64; k += 2) {
            float2 w = make_float2(W1[k * 128 + u] + W2[k * 128 + u],
                                   W1[(k + 1) * 128 + u] + W2[(k + 1) * 128 + u]);
            uint32_t hi, lo;
            split2(w, hi, lo);
            *(uint32_t*)(smem + S_WHI + (u * WPAD + k) * 2) = hi;
            *(uint32_t*)(smem + S_WLO + (u * WPAD + k) * 2) = lo;
        }
    }
    __syncthreads();

    for (int tile = blockIdx.x; tile < NT; tile += GRID) {
        // ---- load x tile (LDG) + split to bf16 hi/lo images ----
        {
            const float4* xt = (const float4*)(x + (size_t)tile * TM * DD);
            float4 v[8];
#pragma unroll
            for (int n = 0; n < 8; n++) v[n] = xt[tid + n * 256];   // MLP=8
#pragma unroll
            for (int n = 0; n < 8; n++) {
                const int i4 = tid + n * 256;
                const int r = i4 >> 5, c = (i4 & 31) << 2;
                uint2 hv, lv;
                split2(make_float2(v[n].x, v[n].y), hv.x, lv.x);
                split2(make_float2(v[n].z, v[n].w), hv.y, lv.y);
                const int off = (r * WPAD + c) * 2;
                *(uint2*)(smem + S_XHI + off) = hv;
                *(uint2*)(smem + S_XLO + off) = lv;
            }
        }
        __syncthreads();

        // ---- mainloop: 3-term bf16 split; rows wm*32.., cols wn*32.. ----
        float acc[2][4][4];
#pragma unroll
        for (int t = 0; t < 2; t++)
#pragma unroll
            for (int j = 0; j < 4; j++)
#pragma unroll
                for (int e = 0; e < 4; e++) acc[t][j][e] = 0.f;

#pragma unroll
        for (int ks = 0; ks < 8; ks++) {
            const int k0 = ks * 16;
            uint32_t ah[2][4], al[2][4];
#pragma unroll
            for (int t = 0; t < 2; t++) {
                const int roff = ((wm * 32 + t * 16 + g) * WPAD + k0 + 2 * q) * 2;
                const char* ph = smem + S_XHI + roff;
                const char* pl = smem + S_XLO + roff;
                ah[t][0] = *(const uint32_t*)(ph);
                ah[t][1] = *(const uint32_t*)(ph + 8 * WPAD * 2);
                ah[t][2] = *(const uint32_t*)(ph + 16);
                ah[t][3] = *(const uint32_t*)(ph + 8 * WPAD * 2 + 16);
                al[t][0] = *(const uint32_t*)(pl);
                al[t][1] = *(const uint32_t*)(pl + 8 * WPAD * 2);
                al[t][2] = *(const uint32_t*)(pl + 16);
                al[t][3] = *(const uint32_t*)(pl + 8 * WPAD * 2 + 16);
            }
#pragma unroll
            for (int j = 0; j < 4; j++) {
                const int boff = ((wn * 32 + j * 8 + g) * WPAD + k0 + 2 * q) * 2;
                uint32_t bh[2], bl[2];
                bh[0] = *(const uint32_t*)(smem + S_WHI + boff);
                bh[1] = *(const uint32_t*)(smem + S_WHI + boff + 16);
                bl[0] = *(const uint32_t*)(smem + S_WLO + boff);
                bl[1] = *(const uint32_t*)(smem + S_WLO + boff + 16);
                mma16816(acc[0][j], ah[0], bh);
                mma16816(acc[1][j], ah[1], bh);
                mma16816(acc[0][j], ah[0], bl);
                mma16816(acc[1][j], ah[1], bl);
                mma16816(acc[0][j], al[0], bh);
                mma16816(acc[1][j], al[1], bh);
            }
        }

        // ---- epilogue: tanh + V-dot -> per-warp partial scores ----
        const float* sBias = (const float*)(smem + S_BIAS);
        const float* sV = (const float*)(smem + S_V);
        float p[4] = {0.f, 0.f, 0.f, 0.f};
#pragma unroll
        for (int t = 0; t < 2; t++) {
#pragma unroll
            for (int j = 0; j < 4; j++) {
                const int u0 = wn * 32 + j * 8 + 2 * q;
                const float bia0 = sBias[u0], bia1 = sBias[u0 + 1];
                const float v0 = sV[u0], v1 = sV[u0 + 1];
                p[t * 2 + 0] += tanh_ap(acc[t][j][0] + bia0) * v0
                              + tanh_ap(acc[t][j][1] + bia1) * v1;
                p[t * 2 + 1] += tanh_ap(acc[t][j][2] + bia0) * v0
                              + tanh_ap(acc[t][j][3] + bia1) * v1;
            }
        }
#pragma unroll
        for (int e = 0; e < 4; e++) {
            p[e] += __shfl_xor_sync(~0u, p[e], 1);
            p[e] += __shfl_xor_sync(~0u, p[e], 2);
        }
        if (q == 0) {
            float* part = (float*)(smem + S_PART);
            part[wn * 64 + wm * 32 + g]      = p[0];
            part[wn * 64 + wm * 32 + g + 8]  = p[1];
            part[wn * 64 + wm * 32 + 16 + g]      = p[2];
            part[wn * 64 + wm * 32 + 16 + g + 8]  = p[3];
        }
        __syncthreads();
        float* sc = (float*)(smem + S_SC);
        if (tid < TM) {
            const float* part = (const float*)(smem + S_PART);
            sc[tid] = part[tid] + part[64 + tid] + part[128 + tid] + part[192 + tid];
        }
        __syncthreads();

        // ---- tile softmax stats (64 scores) ----
        float* red = (float*)(smem + S_RED);
        {
            float v = sc[tid & 63];
#pragma unroll
            for (int off = 16; off > 0; off >>= 1) v = fmaxf(v, __shfl_xor_sync(~0u, v, off));
            if (lane == 0) red[wid] = v;
        }
        __syncthreads();
        const float M = fmaxf(red[0], red[1]);     // warps 0,1 cover sc[0..31],[32..63]
        __syncthreads();
        {
            float v = __expf(sc[tid & 63] - M);
#pragma unroll
            for (int off = 16; off > 0; off >>= 1) v += __shfl_xor_sync(~0u, v, off);
            if (lane == 0) red[wid] = v;
            if (tid < TM) sc[tid] = __expf(sc[tid] - M);
        }
        __syncthreads();
        const float S = red[0] + red[1];

        // ---- tile context from hi+lo images ----
        {
            const int h = tid >> 6;          // 4 groups x 16 tokens
            const int pp = tid & 63;         // d-pair
            float2 cacc = make_float2(0.f, 0.f);
#pragma unroll
            for (int i = 0; i < 16; i++) {
                const int t = h * 16 + i;
                const float a = sc[t];
                const int off = (t * WPAD + 2 * pp) * 2;
                float2 fh = __bfloat1622float2(*(const __nv_bfloat162*)(smem + S_XHI + off));
                float2 fl = __bfloat1622float2(*(const __nv_bfloat162*)(smem + S_XLO + off));
                cacc.x = fmaf(a, fh.x + fl.x, cacc.x);
                cacc.y = fmaf(a, fh.y + fl.y, cacc.y);
            }
            ((float2*)(smem + S_CTX))[h * 64 + pp] = cacc;
        }
        __syncthreads();
        float* gout = g_tile + (size_t)tile * TSTRIDE;
        if (tid < 128) {
            const float* cp = (const float*)(smem + S_CTX);
            gout[tid] = cp[tid] + cp[128 + tid] + cp[256 + tid] + cp[384 + tid];
        }
        if (tid == 128) gout[128] = M;
        if (tid == 129) gout[129] = S;
        __threadfence();                     // make tile results device-visible
        __syncthreads();

        // ---- per-batch counter; the 32nd finisher combines this batch ----
        const int b = tile >> 5;
        if (tid == 0) {
            unsigned int old = atomicAdd(&g_bdone[b], 1u);
            ((int*)(smem + S_FLAG))[0] = (old == NTILE - 1);
        }
        __syncthreads();
        if (((int*)(smem + S_FLAG))[0]) {
            __threadfence();                 // acquire other CTAs' tile writes
            float* cw = (float*)(smem + S_CW);
            if (tid < 32) {
                const float* tb = g_tile + (size_t)b * NTILE * TSTRIDE;
                float ms = tb[tid * TSTRIDE + 128];
                float Mb = ms;
#pragma unroll
                for (int off = 16; off > 0; off >>= 1)
                    Mb = fmaxf(Mb, __shfl_xor_sync(~0u, Mb, off));
                const float w = __expf(ms - Mb);
                float Sb = tb[tid * TSTRIDE + 129] * w;
#pragma unroll
                for (int off = 16; off > 0; off >>= 1)
                    Sb += __shfl_xor_sync(~0u, Sb, off);
                cw[tid] = w;
                if (tid == 0) {
                    ((float*)(smem + S_CIS))[0] = 1.f / Sb;
                    g_bdone[b] = 0;          // reset for next graph replay
                }
            }
            __syncthreads();
            if (tid < 128) {
                const float* tb = g_tile + (size_t)b * NTILE * TSTRIDE;
                const float inv = ((const float*)(smem + S_CIS))[0];
                float a = 0.f;
#pragma unroll
                for (int s = 0; s < NTILE; s++)
                    a = fmaf(tb[s * TSTRIDE + tid], cw[s], a);
                out[(size_t)b * DD + tid] = a * inv;
            }
        }
        __syncthreads();                     // protect smem before next tile
    }
}

// ---------------------------------------------------------------------------
extern "C" void kernel_launch(void* const* d_in, const int* in_sizes, int n_in,
                              void* d_out, int out_size) {
    const float* enc = (const float*)d_in[0];
    const float* W1w = (const float*)d_in[1];
    const float* W1b = (const float*)d_in[2];
    const float* W2w = (const float*)d_in[3];
    const float* W2b = (const float*)d_in[4];
    const float* Vw  = (const float*)d_in[5];
    // d_in[6] = V_b: softmax-invariant.
    float* out = (float*)d_out;

    cudaFuncSetAttribute(fused_kernel, cudaFuncAttributeMaxDynamicSharedMemorySize, S_TOTAL);
    fused_kernel<<<GRID, 256, S_TOTAL>>>(enc, W1w, W2w, W1b, W2b, Vw, out);
}

// round 12
// speedup vs baseline: 1.1161x; 1.1161x over previous
#include <cuda_runtime.h>
#include <cuda_fp16.h>
#include <math.h>
#include <stdint.h>

#define BB 64
#define TT 2048
#define DD 128
#define UU 128
#define WPAD 136                        // padded fp16 row -> conflict-free frags
#define NTILE 16
#define NT (BB * NTILE)                 // 1024 tiles
#define GRID 148
#define TSTRIDE 132                     // 128 ctx + M + S + pad

__device__ float g_tile[NT * TSTRIDE];
__device__ unsigned int g_done;

// ---- smem layout (bytes) ----
#define S_BIAS 0                        // float[128]
#define S_V    512                      // float[128]
#define S_PART 1024                     // float[2][128]
#define S_SC   2048                     // float[128]
#define S_RED  2560                     // float[8]
#define S_FLAG 2624
#define S_CTX  2688                     // float[4][128]
#define S_CMB  4736                     // wgt[64][16] + invS[64] = 4352
#define S_RAW  9216                     // float[128][128] = 65536
#define S_XH   (S_RAW + 65536)          // fp16[128][WPAD] = 34816
#define S_XL   (S_XH + 34816)           // fp16 lo image (ctx only)
#define S_WHI  (S_XL + 34816)
#define S_WLO  (S_WHI + 34816)
#define S_TOTAL (S_WLO + 34816)         // 213504 B

__device__ __forceinline__ uint32_t smem_u32(const void* p) {
    uint32_t a;
    asm("{ .reg .u64 t; cvta.to.shared.u64 t, %1; cvt.u32.u64 %0, t; }" : "=r"(a) : "l"(p));
    return a;
}
#define CP_ASYNC16(dst, src) \
    asm volatile("cp.async.cg.shared.global [%0], [%1], 16;" :: "r"(dst), "l"(src) : "memory")
#define CP_COMMIT() asm volatile("cp.async.commit_group;" ::: "memory")
#define CP_WAIT0()  asm volatile("cp.async.wait_group 0;" ::: "memory")

__device__ __forceinline__ void mma16816(float* c, const uint32_t* a, const uint32_t* b) {
    asm volatile(
        "mma.sync.aligned.m16n8k16.row.col.f32.f16.f16.f32 "
        "{%0,%1,%2,%3}, {%4,%5,%6,%7}, {%8,%9}, {%0,%1,%2,%3};"
        : "+f"(c[0]), "+f"(c[1]), "+f"(c[2]), "+f"(c[3])
        : "r"(a[0]), "r"(a[1]), "r"(a[2]), "r"(a[3]), "r"(b[0]), "r"(b[1]));
}
__device__ __forceinline__ float tanh_ap(float x) {
    float r;
    asm("tanh.approx.f32 %0, %1;" : "=f"(r) : "f"(x));
    return r;
}
// fp16 hi/lo split of a float2 (packed half2 results)
__device__ __forceinline__ void split2h(float2 v, uint32_t& hi, uint32_t& lo) {
    __half2 h = __float22half2_rn(v);
    float2 hf = __half22float2(h);
    __half2 l = __float22half2_rn(make_float2(v.x - hf.x, v.y - hf.y));
    hi = *(uint32_t*)&h;
    lo = *(uint32_t*)&l;
}

__global__ void __launch_bounds__(256, 1) fused_kernel(const float* __restrict__ x,
                                                       const float* __restrict__ W1,
                                                       const float* __restrict__ W2,
                                                       const float* __restrict__ b1,
                                                       const float* __restrict__ b2,
                                                       const float* __restrict__ Vw,
                                                       float* __restrict__ out) {
    extern __shared__ __align__(16) char smem[];
    const int tid = threadIdx.x, wid = tid >> 5, lane = tid & 31;
    const int g = lane >> 2, q = lane & 3;
    const int wm = wid & 3, wn = wid >> 2;       // 4x2 warp grid: 32x64 out tiles
    float* rawf = (float*)(smem + S_RAW);

    // ---- one-time: bias/V ; Wsum -> fp16 transpose-split into WHI/WLO ----
    if (tid < 128) {
        ((float*)(smem + S_BIAS))[tid] = b1[tid] + b2[tid];
        ((float*)(smem + S_V))[tid] = Vw[tid];
    }
    {
        const float4* w1 = (const float4*)W1;
        const float4* w2 = (const float4*)W2;
        float4* r4 = (float4*)rawf;
#pragma unroll
        for (int i = tid; i < 4096; i += 256) {
            float4 a = w1[i], b = w2[i];
            float4 c;
            c.x = a.x + b.x; c.y = a.y + b.y; c.z = a.z + b.z; c.w = a.w + b.w;
            r4[i] = c;
        }
    }
    __syncthreads();
    {
        const int u = tid & 127;
        const int k0 = (tid >> 7) * 64;
#pragma unroll
        for (int k = k0; k < k0 + 64; k += 2) {
            float2 w = make_float2(rawf[k * 128 + u], rawf[(k + 1) * 128 + u]);
            uint32_t hi, lo;
            split2h(w, hi, lo);
            *(uint32_t*)(smem + S_WHI + (u * WPAD + k) * 2) = hi;
            *(uint32_t*)(smem + S_WLO + (u * WPAD + k) * 2) = lo;
        }
    }
    __syncthreads();

    // ---- prologue: fetch first tile ----
    const uint32_t raw_addr = smem_u32(smem + S_RAW);
    int tile = blockIdx.x;
    if (tile < NT) {
        const char* src = (const char*)(x + (size_t)tile * 16384) + tid * 16;
#pragma unroll
        for (int n = 0; n < 16; n++)
            CP_ASYNC16(raw_addr + tid * 16 + n * 4096, src + n * 4096);
        CP_COMMIT();
    }

    for (; tile < NT; tile += GRID) {
        CP_WAIT0();
        __syncthreads();

        // ---- convert raw fp32 -> fp16 hi image (+ lo image for ctx) ----
#pragma unroll
        for (int i4 = tid; i4 < 4096; i4 += 256) {
            int r = i4 >> 5;
            int c = (i4 & 31) << 2;
            float4 v = ((const float4*)rawf)[i4];
            uint2 hv, lv;
            split2h(make_float2(v.x, v.y), hv.x, lv.x);
            split2h(make_float2(v.z, v.w), hv.y, lv.y);
            size_t off = ((size_t)r * WPAD + c) * 2;
            *(uint2*)(smem + S_XH + off) = hv;
            *(uint2*)(smem + S_XL + off) = lv;
        }
        __syncthreads();

        // ---- prefetch next tile into raw (overlaps mainloop+epilogue) ----
        {
            const int next = tile + GRID;
            if (next < NT) {
                const char* src = (const char*)(x + (size_t)next * 16384) + tid * 16;
#pragma unroll
                for (int n = 0; n < 16; n++)
                    CP_ASYNC16(raw_addr + tid * 16 + n * 4096, src + n * 4096);
                CP_COMMIT();
            }
        }

        // ---- mainloop: 2-term fp16 (Xh*Whi + Xh*Wlo) ----
        float acc[2][8][4];
#pragma unroll
        for (int t = 0; t < 2; t++)
#pragma unroll
            for (int j = 0; j < 8; j++)
#pragma unroll
                for (int e = 0; e < 4; e++) acc[t][j][e] = 0.f;

#pragma unroll
        for (int ks = 0; ks < 8; ks++) {
            const int k0 = ks * 16;
            uint32_t ah[2][4];
#pragma unroll
            for (int t = 0; t < 2; t++) {
                const int roff = ((wm * 32 + t * 16 + g) * WPAD + k0 + 2 * q) * 2;
                const char* ph = smem + S_XH + roff;
                ah[t][0] = *(const uint32_t*)(ph);
                ah[t][1] = *(const uint32_t*)(ph + 8 * WPAD * 2);
                ah[t][2] = *(const uint32_t*)(ph + 16);
                ah[t][3] = *(const uint32_t*)(ph + 8 * WPAD * 2 + 16);
            }
#pragma unroll
            for (int j = 0; j < 8; j++) {
                const int boff = ((wn * 64 + j * 8 + g) * WPAD + k0 + 2 * q) * 2;
                uint32_t bh[2], bl[2];
                bh[0] = *(const uint32_t*)(smem + S_WHI + boff);
                bh[1] = *(const uint32_t*)(smem + S_WHI + boff + 16);
                bl[0] = *(const uint32_t*)(smem + S_WLO + boff);
                bl[1] = *(const uint32_t*)(smem + S_WLO + boff + 16);
                mma16816(acc[0][j], ah[0], bh);
                mma16816(acc[1][j], ah[1], bh);
                mma16816(acc[0][j], ah[0], bl);
                mma16816(acc[1][j], ah[1], bl);
            }
        }

        // ---- epilogue: tanh + V-dot -> tile scores ----
        const float* sBias = (const float*)(smem + S_BIAS);
        const float* sV = (const float*)(smem + S_V);
        float p[4] = {0.f, 0.f, 0.f, 0.f};
#pragma unroll
        for (int t = 0; t < 2; t++) {
#pragma unroll
            for (int j = 0; j < 8; j++) {
                const int u0 = wn * 64 + j * 8 + 2 * q;
                const float bia0 = sBias[u0], bia1 = sBias[u0 + 1];
                const float v0 = sV[u0], v1 = sV[u0 + 1];
                p[t * 2 + 0] += tanh_ap(acc[t][j][0] + bia0) * v0
                              + tanh_ap(acc[t][j][1] + bia1) * v1;
                p[t * 2 + 1] += tanh_ap(acc[t][j][2] + bia0) * v0
                              + tanh_ap(acc[t][j][3] + bia1) * v1;
            }
        }
#pragma unroll
        for (int e = 0; e < 4; e++) {
            p[e] += __shfl_xor_sync(~0u, p[e], 1);
            p[e] += __shfl_xor_sync(~0u, p[e], 2);
        }
        if (q == 0) {
            float* part = (float*)(smem + S_PART);
            part[wn * 128 + wm * 32 + g]      = p[0];
            part[wn * 128 + wm * 32 + g + 8]  = p[1];
            part[wn * 128 + wm * 32 + g + 16] = p[2];
            part[wn * 128 + wm * 32 + g + 24] = p[3];
        }
        __syncthreads();
        float* sc = (float*)(smem + S_SC);
        if (tid < 128) {
            const float* part = (const float*)(smem + S_PART);
            sc[tid] = part[tid] + part[128 + tid];
        }
        __syncthreads();

        // ---- tile softmax stats ----
        float* red = (float*)(smem + S_RED);
        {
            float v = sc[tid & 127];
#pragma unroll
            for (int off = 16; off > 0; off >>= 1) v = fmaxf(v, __shfl_xor_sync(~0u, v, off));
            if (lane == 0) red[wid] = v;
        }
        __syncthreads();
        float M = fmaxf(fmaxf(red[0], red[1]), fmaxf(red[2], red[3]));
        M = fmaxf(M, fmaxf(fmaxf(red[4], red[5]), fmaxf(red[6], red[7])));
        __syncthreads();
        float e_val = 0.f;
        if (tid < 128) e_val = __expf(sc[tid] - M);
        {
            float v = e_val;
#pragma unroll
            for (int off = 16; off > 0; off >>= 1) v += __shfl_xor_sync(~0u, v, off);
            if (lane == 0) red[wid] = v;
        }
        if (tid < 128) sc[tid] = e_val;
        __syncthreads();
        const float S = red[0] + red[1] + red[2] + red[3];

        // ---- tile context from hi+lo fp16 images (exact to 2^-22) ----
        {
            const int h = tid >> 6;          // 4 groups x 32 tokens
            const int pp = tid & 63;         // d-pair
            float2 cacc = make_float2(0.f, 0.f);
#pragma unroll 8
            for (int i = 0; i < 32; i++) {
                const int t = h * 32 + i;
                const float a = sc[t];
                const int off = (t * WPAD + 2 * pp) * 2;
                float2 fh = __half22float2(*(const __half2*)(smem + S_XH + off));
                float2 fl = __half22float2(*(const __half2*)(smem + S_XL + off));
                cacc.x = fmaf(a, fh.x + fl.x, cacc.x);
                cacc.y = fmaf(a, fh.y + fl.y, cacc.y);
            }
            ((float2*)(smem + S_CTX))[h * 64 + pp] = cacc;
        }
        __syncthreads();
        float* gout = g_tile + (size_t)tile * TSTRIDE;
        if (tid < 128) {
            const float* cp = (const float*)(smem + S_CTX);
            gout[tid] = cp[tid] + cp[128 + tid] + cp[256 + tid] + cp[384 + tid];
        }
        if (tid == 128) gout[128] = M;
        if (tid == 129) gout[129] = S;
        __syncthreads();
    }

    // ---- last CTA combines all tiles -> out ----
    __threadfence();
    if (tid == 0) {
        unsigned int old = atomicAdd(&g_done, 1u);
        ((int*)(smem + S_FLAG))[0] = (old == (unsigned int)(gridDim.x - 1));
    }
    __syncthreads();
    if (!((int*)(smem + S_FLAG))[0]) return;
    __threadfence();

    float* wgt = (float*)(smem + S_CMB);            // [64][16]
    float* invS = (float*)(smem + S_CMB + 4096);    // [64]
    if (tid < 64) {
        const float* tb = g_tile + (size_t)tid * NTILE * TSTRIDE;
        float M = -1e30f;
#pragma unroll
        for (int s = 0; s < NTILE; s++) M = fmaxf(M, tb[s * TSTRIDE + 128]);
        float S = 0.f;
#pragma unroll
        for (int s = 0; s < NTILE; s++) {
            float w = __expf(tb[s * TSTRIDE + 128] - M);
            wgt[tid * NTILE + s] = w;
            S = fmaf(tb[s * TSTRIDE + 129], w, S);
        }
        invS[tid] = 1.f / S;
    }
    __syncthreads();
#pragma unroll 4
    for (int iter = 0; iter < 32; iter++) {
        const int b = iter * 2 + (tid >> 7);
        const int d = tid & 127;
        const float* tb = g_tile + (size_t)b * NTILE * TSTRIDE;
        const float* wb = wgt + b * NTILE;
        float a = 0.f;
#pragma unroll
        for (int s = 0; s < NTILE; s++) a = fmaf(tb[s * TSTRIDE + d], wb[s], a);
        out[(size_t)b * DD + d] = a * invS[b];
    }
    if (tid == 0) g_done = 0;   // reset for next graph replay
}

// ---------------------------------------------------------------------------
extern "C" void kernel_launch(void* const* d_in, const int* in_sizes, int n_in,
                              void* d_out, int out_size) {
    const float* enc = (const float*)d_in[0];
    const float* W1w = (const float*)d_in[1];
    const float* W1b = (const float*)d_in[2];
    const float* W2w = (const float*)d_in[3];
    const float* W2b = (const float*)d_in[4];
    const float* Vw  = (const float*)d_in[5];
    // d_in[6] = V_b: softmax-invariant.
    float* out = (float*)d_out;

    cudaFuncSetAttribute(fused_kernel, cudaFuncAttributeMaxDynamicSharedMemorySize, S_TOTAL);
    fused_kernel<<<GRID, 256, S_TOTAL>>>(enc, W1w, W2w, W1b, W2b, Vw, out);
}

// round 13
// speedup vs baseline: 1.2784x; 1.1454x over previous
#include <cuda_runtime.h>
#include <cuda_fp16.h>
#include <math.h>
#include <stdint.h>

#define BB 64
#define TT 2048
#define DD 128
#define UU 128
#define WPAD 136                        // padded fp16 row -> conflict-free frags
#define TM 64                           // tokens per tile
#define NTILE 32                        // tiles per batch
#define NT (BB * NTILE)                 // 2048 tiles
#define GRID 296                        // 148 SMs x 2 CTAs
#define TSTRIDE 132                     // 128 ctx + M + S + pad

__device__ float g_tile[NT * TSTRIDE];
__device__ unsigned int g_done;

// ---- smem layout (bytes), total 98304 B -> 2 CTAs/SM ----
#define S_BIAS 0                        // float[128]
#define S_V    512                      // float[128]
#define S_PART 1024                     // float[4][64]
#define S_SC   2048                     // float[64]
#define S_RED  2304                     // float[8]
#define S_FLAG 2368                     // int (pad)
#define S_CTX  2432                     // float[4][128]
#define S_CMB  4480                     // wgt[64][32]=8192 + invS[64]=256
#define S_RAW  13312                    // float[64][128] = 32768
#define S_XH   (S_RAW + 32768)         // fp16[64][WPAD] = 17408
#define S_WHI  (S_XH + 17408)          // fp16[128][WPAD] = 34816
#define S_TOTAL (S_WHI + 34816)        // 98304

__device__ __forceinline__ uint32_t smem_u32(const void* p) {
    uint32_t a;
    asm("{ .reg .u64 t; cvta.to.shared.u64 t, %1; cvt.u32.u64 %0, t; }" : "=r"(a) : "l"(p));
    return a;
}
#define CP_ASYNC16(dst, src) \
    asm volatile("cp.async.cg.shared.global [%0], [%1], 16;" :: "r"(dst), "l"(src) : "memory")
#define CP_COMMIT() asm volatile("cp.async.commit_group;" ::: "memory")
#define CP_WAIT0()  asm volatile("cp.async.wait_group 0;" ::: "memory")

__device__ __forceinline__ void mma16816(float* c, const uint32_t* a, const uint32_t* b) {
    asm volatile(
        "mma.sync.aligned.m16n8k16.row.col.f32.f16.f16.f32 "
        "{%0,%1,%2,%3}, {%4,%5,%6,%7}, {%8,%9}, {%0,%1,%2,%3};"
        : "+f"(c[0]), "+f"(c[1]), "+f"(c[2]), "+f"(c[3])
        : "r"(a[0]), "r"(a[1]), "r"(a[2]), "r"(a[3]), "r"(b[0]), "r"(b[1]));
}
__device__ __forceinline__ float tanh_ap(float x) {
    float r;
    asm("tanh.approx.f32 %0, %1;" : "=f"(r) : "f"(x));
    return r;
}

__global__ void __launch_bounds__(256, 2) fused_kernel(const float* __restrict__ x,
                                                       const float* __restrict__ W1,
                                                       const float* __restrict__ W2,
                                                       const float* __restrict__ b1,
                                                       const float* __restrict__ b2,
                                                       const float* __restrict__ Vw,
                                                       float* __restrict__ out) {
    extern __shared__ __align__(16) char smem[];
    const int tid = threadIdx.x, wid = tid >> 5, lane = tid & 31;
    const int g = lane >> 2, q = lane & 3;
    const int wm = wid & 1, wn = wid >> 1;       // 2x4 warp grid: 32x32 out tiles
    float* rawf = (float*)(smem + S_RAW);

    // ---- one-time: bias/V ; Wsum -> fp16 image (coalesced along u) ----
    if (tid < 128) {
        ((float*)(smem + S_BIAS))[tid] = b1[tid] + b2[tid];
        ((float*)(smem + S_V))[tid] = Vw[tid];
    }
    {
        const int u = tid & 127;
        const int k0 = (tid >> 7) * 64;
#pragma unroll
        for (int k = k0; k < k0 + 64; k += 2) {
            float2 w = make_float2(W1[k * 128 + u] + W2[k * 128 + u],
                                   W1[(k + 1) * 128 + u] + W2[(k + 1) * 128 + u]);
            __half2 h = __float22half2_rn(w);
            *(uint32_t*)(smem + S_WHI + (u * WPAD + k) * 2) = *(uint32_t*)&h;
        }
    }
    __syncthreads();

    // ---- prologue: fetch first tile (32 KB) ----
    const uint32_t raw_addr = smem_u32(smem + S_RAW);
    int tile = blockIdx.x;
    if (tile < NT) {
        const char* src = (const char*)(x + (size_t)tile * TM * DD) + tid * 16;
#pragma unroll
        for (int n = 0; n < 8; n++)
            CP_ASYNC16(raw_addr + tid * 16 + n * 4096, src + n * 4096);
        CP_COMMIT();
    }

    for (; tile < NT; tile += GRID) {
        CP_WAIT0();
        __syncthreads();

        // ---- convert raw fp32 -> fp16 image (single RN) ----
#pragma unroll
        for (int i4 = tid; i4 < 2048; i4 += 256) {
            int r = i4 >> 5;
            int c = (i4 & 31) << 2;
            float4 v = ((const float4*)rawf)[i4];
            __half2 h0 = __float22half2_rn(make_float2(v.x, v.y));
            __half2 h1 = __float22half2_rn(make_float2(v.z, v.w));
            uint2 hv;
            hv.x = *(uint32_t*)&h0;
            hv.y = *(uint32_t*)&h1;
            *(uint2*)(smem + S_XH + ((size_t)r * WPAD + c) * 2) = hv;
        }
        __syncthreads();

        // ---- prefetch next tile into raw (overlaps rest of this tile) ----
        {
            const int next = tile + GRID;
            if (next < NT) {
                const char* src = (const char*)(x + (size_t)next * TM * DD) + tid * 16;
#pragma unroll
                for (int n = 0; n < 8; n++)
                    CP_ASYNC16(raw_addr + tid * 16 + n * 4096, src + n * 4096);
                CP_COMMIT();
            }
        }

        // ---- mainloop: single-term fp16 MMA ----
        float acc[2][4][4];
#pragma unroll
        for (int t = 0; t < 2; t++)
#pragma unroll
            for (int j = 0; j < 4; j++)
#pragma unroll
                for (int e = 0; e < 4; e++) acc[t][j][e] = 0.f;

#pragma unroll
        for (int ks = 0; ks < 8; ks++) {
            const int k0 = ks * 16;
            uint32_t ah[2][4];
#pragma unroll
            for (int t = 0; t < 2; t++) {
                const int roff = ((wm * 32 + t * 16 + g) * WPAD + k0 + 2 * q) * 2;
                const char* ph = smem + S_XH + roff;
                ah[t][0] = *(const uint32_t*)(ph);
                ah[t][1] = *(const uint32_t*)(ph + 8 * WPAD * 2);
                ah[t][2] = *(const uint32_t*)(ph + 16);
                ah[t][3] = *(const uint32_t*)(ph + 8 * WPAD * 2 + 16);
            }
#pragma unroll
            for (int j = 0; j < 4; j++) {
                const int boff = ((wn * 32 + j * 8 + g) * WPAD + k0 + 2 * q) * 2;
                uint32_t bh[2];
                bh[0] = *(const uint32_t*)(smem + S_WHI + boff);
                bh[1] = *(const uint32_t*)(smem + S_WHI + boff + 16);
                mma16816(acc[0][j], ah[0], bh);
                mma16816(acc[1][j], ah[1], bh);
            }
        }

        // ---- epilogue: tanh + V-dot -> tile scores ----
        const float* sBias = (const float*)(smem + S_BIAS);
        const float* sV = (const float*)(smem + S_V);
        float p[4] = {0.f, 0.f, 0.f, 0.f};
#pragma unroll
        for (int t = 0; t < 2; t++) {
#pragma unroll
            for (int j = 0; j < 4; j++) {
                const int u0 = wn * 32 + j * 8 + 2 * q;
                const float bia0 = sBias[u0], bia1 = sBias[u0 + 1];
                const float v0 = sV[u0], v1 = sV[u0 + 1];
                p[t * 2 + 0] += tanh_ap(acc[t][j][0] + bia0) * v0
                              + tanh_ap(acc[t][j][1] + bia1) * v1;
                p[t * 2 + 1] += tanh_ap(acc[t][j][2] + bia0) * v0
                              + tanh_ap(acc[t][j][3] + bia1) * v1;
            }
        }
#pragma unroll
        for (int e = 0; e < 4; e++) {
            p[e] += __shfl_xor_sync(~0u, p[e], 1);
            p[e] += __shfl_xor_sync(~0u, p[e], 2);
        }
        if (q == 0) {
            float* part = (float*)(smem + S_PART);
            part[wn * 64 + wm * 32 + g]          = p[0];
            part[wn * 64 + wm * 32 + g + 8]      = p[1];
            part[wn * 64 + wm * 32 + 16 + g]     = p[2];
            part[wn * 64 + wm * 32 + 16 + g + 8] = p[3];
        }
        __syncthreads();
        float* sc = (float*)(smem + S_SC);
        if (tid < TM) {
            const float* part = (const float*)(smem + S_PART);
            sc[tid] = part[tid] + part[64 + tid] + part[128 + tid] + part[192 + tid];
        }
        __syncthreads();

        // ---- tile softmax stats (64 scores) ----
        float* red = (float*)(smem + S_RED);
        {
            float v = sc[tid & 63];
#pragma unroll
            for (int off = 16; off > 0; off >>= 1) v = fmaxf(v, __shfl_xor_sync(~0u, v, off));
            if (lane == 0) red[wid] = v;
        }
        __syncthreads();
        const float M = fmaxf(red[0], red[1]);
        __syncthreads();
        {
            float v = __expf(sc[tid & 63] - M);
#pragma unroll
            for (int off = 16; off > 0; off >>= 1) v += __shfl_xor_sync(~0u, v, off);
            if (lane == 0) red[wid] = v;
            if (tid < TM) sc[tid] = __expf(sc[tid] - M);
        }
        __syncthreads();
        const float S = red[0] + red[1];

        // ---- tile context from XH (fp16 RN image) ----
        {
            const int h = tid >> 6;          // 4 groups x 16 tokens
            const int pp = tid & 63;         // d-pair
            float2 cacc = make_float2(0.f, 0.f);
#pragma unroll
            for (int i = 0; i < 16; i++) {
                const int t = h * 16 + i;
                const float a = sc[t];
                float2 fh = __half22float2(
                    *(const __half2*)(smem + S_XH + (t * WPAD + 2 * pp) * 2));
                cacc.x = fmaf(a, fh.x, cacc.x);
                cacc.y = fmaf(a, fh.y, cacc.y);
            }
            ((float2*)(smem + S_CTX))[h * 64 + pp] = cacc;
        }
        __syncthreads();
        float* gout = g_tile + (size_t)tile * TSTRIDE;
        if (tid < 128) {
            const float* cp = (const float*)(smem + S_CTX);
            gout[tid] = cp[tid] + cp[128 + tid] + cp[256 + tid] + cp[384 + tid];
        }
        if (tid == 128) gout[128] = M;
        if (tid == 129) gout[129] = S;
        __syncthreads();
    }

    // ---- last CTA combines all tiles -> out ----
    __threadfence();
    if (tid == 0) {
        unsigned int old = atomicAdd(&g_done, 1u);
        ((int*)(smem + S_FLAG))[0] = (old == (unsigned int)(gridDim.x - 1));
    }
    __syncthreads();
    if (!((int*)(smem + S_FLAG))[0]) return;
    __threadfence();

    float* wgt = (float*)(smem + S_CMB);            // [64][32]
    float* invS = (float*)(smem + S_CMB + 8192);    // [64]
    if (tid < 64) {
        const float* tb = g_tile + (size_t)tid * NTILE * TSTRIDE;
        float M = -1e30f;
#pragma unroll
        for (int s = 0; s < NTILE; s++) M = fmaxf(M, tb[s * TSTRIDE + 128]);
        float S = 0.f;
#pragma unroll
        for (int s = 0; s < NTILE; s++) {
            float w = __expf(tb[s * TSTRIDE + 128] - M);
            wgt[tid * NTILE + s] = w;
            S = fmaf(tb[s * TSTRIDE + 129], w, S);
        }
        invS[tid] = 1.f / S;
    }
    __syncthreads();
#pragma unroll 4
    for (int iter = 0; iter < 32; iter++) {
        const int b = iter * 2 + (tid >> 7);
        const int d = tid & 127;
        const float* tb = g_tile + (size_t)b * NTILE * TSTRIDE;
        const float* wb = wgt + b * NTILE;
        float a = 0.f;
#pragma unroll
        for (int s = 0; s < NTILE; s++) a = fmaf(tb[s * TSTRIDE + d], wb[s], a);
        out[(size_t)b * DD + d] = a * invS[b];
    }
    if (tid == 0) g_done = 0;   // reset for next graph replay
}

// ---------------------------------------------------------------------------
extern "C" void kernel_launch(void* const* d_in, const int* in_sizes, int n_in,
                              void* d_out, int out_size) {
    const float* enc = (const float*)d_in[0];
    const float* W1w = (const float*)d_in[1];
    const float* W1b = (const float*)d_in[2];
    const float* W2w = (const float*)d_in[3];
    const float* W2b = (const float*)d_in[4];
    const float* Vw  = (const float*)d_in[5];
    // d_in[6] = V_b: softmax-invariant.
    float* out = (float*)d_out;

    cudaFuncSetAttribute(fused_kernel, cudaFuncAttributeMaxDynamicSharedMemorySize, S_TOTAL);
    fused_kernel<<<GRID, 256, S_TOTAL>>>(enc, W1w, W2w, W1b, W2b, Vw, out);
}

// round 14
// speedup vs baseline: 1.4535x; 1.1370x over previous
#include <cuda_runtime.h>
#include <cuda_fp16.h>
#include <math.h>
#include <stdint.h>

#define BB 64
#define TT 2048
#define DD 128
#define UU 128
#define WPAD 136                        // padded fp16 row -> conflict-free frags
#define TM 128                          // tokens per tile
#define NTILE 16                        // tiles per batch
#define NT (BB * NTILE)                 // 1024 tiles
#define GRID 296                        // 148 SMs x 2 CTAs
#define TSTRIDE 132                     // 128 ctx + M + S + pad

__device__ float g_tile[NT * TSTRIDE];
__device__ unsigned int g_done;

// ---- smem layout (bytes), total 78848 B -> 2 CTAs/SM ----
#define S_BIAS 0                        // float[128]
#define S_V    512                      // float[128]
#define S_PART 1024                     // float[2][128]
#define S_SC   2048                     // float[128]
#define S_RED  2560                     // float[8]
#define S_FLAG 2624
#define S_CTX  2688                     // float[4][128] = 2048
#define S_CMB  4736                     // wgt[64][16]=4096 + invS[64]=256
#define S_XH   9216                     // fp16[128][WPAD] = 34816
#define S_WHI  (S_XH + 34816)           // fp16[128][WPAD] = 34816
#define S_TOTAL (S_WHI + 34816)         // 78848

__device__ __forceinline__ void mma16816(float* c, const uint32_t* a, const uint32_t* b) {
    asm volatile(
        "mma.sync.aligned.m16n8k16.row.col.f32.f16.f16.f32 "
        "{%0,%1,%2,%3}, {%4,%5,%6,%7}, {%8,%9}, {%0,%1,%2,%3};"
        : "+f"(c[0]), "+f"(c[1]), "+f"(c[2]), "+f"(c[3])
        : "r"(a[0]), "r"(a[1]), "r"(a[2]), "r"(a[3]), "r"(b[0]), "r"(b[1]));
}
__device__ __forceinline__ float tanh_ap(float x) {
    float r;
    asm("tanh.approx.f32 %0, %1;" : "=f"(r) : "f"(x));
    return r;
}

__global__ void __launch_bounds__(256, 2) fused_kernel(const float* __restrict__ x,
                                                       const float* __restrict__ W1,
                                                       const float* __restrict__ W2,
                                                       const float* __restrict__ b1,
                                                       const float* __restrict__ b2,
                                                       const float* __restrict__ Vw,
                                                       float* __restrict__ out) {
    extern __shared__ __align__(16) char smem[];
    const int tid = threadIdx.x, wid = tid >> 5, lane = tid & 31;
    const int g = lane >> 2, q = lane & 3;
    const int wm = wid & 3, wn = wid >> 2;       // 4x2 warp grid: 32x64 out tiles

    // ---- one-time: bias/V ; Wsum -> fp16 image ----
    if (tid < 128) {
        ((float*)(smem + S_BIAS))[tid] = b1[tid] + b2[tid];
        ((float*)(smem + S_V))[tid] = Vw[tid];
    }
    {
        const int u = tid & 127;
        const int k0 = (tid >> 7) * 64;
#pragma unroll
        for (int k = k0; k < k0 + 64; k += 2) {
            float2 w = make_float2(W1[k * 128 + u] + W2[k * 128 + u],
                                   W1[(k + 1) * 128 + u] + W2[(k + 1) * 128 + u]);
            __half2 h = __float22half2_rn(w);
            *(uint32_t*)(smem + S_WHI + (u * WPAD + k) * 2) = *(uint32_t*)&h;
        }
    }
    __syncthreads();

    for (int tile = blockIdx.x; tile < NT; tile += GRID) {
        // ---- load x tile (LDG, MLP=8 per batch) + convert to fp16 image ----
        {
            const float4* xt = (const float4*)(x + (size_t)tile * TM * DD);
#pragma unroll
            for (int half = 0; half < 2; half++) {
                float4 v[8];
#pragma unroll
                for (int n = 0; n < 8; n++) v[n] = xt[tid + (half * 8 + n) * 256];
#pragma unroll
                for (int n = 0; n < 8; n++) {
                    const int i4 = tid + (half * 8 + n) * 256;
                    const int r = i4 >> 5, c = (i4 & 31) << 2;
                    __half2 h0 = __float22half2_rn(make_float2(v[n].x, v[n].y));
                    __half2 h1 = __float22half2_rn(make_float2(v[n].z, v[n].w));
                    uint2 hv;
                    hv.x = *(uint32_t*)&h0;
                    hv.y = *(uint32_t*)&h1;
                    *(uint2*)(smem + S_XH + ((size_t)r * WPAD + c) * 2) = hv;
                }
            }
        }
        __syncthreads();

        // ---- mainloop: single-term fp16 MMA (rows wm*32.., cols wn*64..) ----
        float acc[2][8][4];
#pragma unroll
        for (int t = 0; t < 2; t++)
#pragma unroll
            for (int j = 0; j < 8; j++)
#pragma unroll
                for (int e = 0; e < 4; e++) acc[t][j][e] = 0.f;

#pragma unroll
        for (int ks = 0; ks < 8; ks++) {
            const int k0 = ks * 16;
            uint32_t ah[2][4];
#pragma unroll
            for (int t = 0; t < 2; t++) {
                const int roff = ((wm * 32 + t * 16 + g) * WPAD + k0 + 2 * q) * 2;
                const char* ph = smem + S_XH + roff;
                ah[t][0] = *(const uint32_t*)(ph);
                ah[t][1] = *(const uint32_t*)(ph + 8 * WPAD * 2);
                ah[t][2] = *(const uint32_t*)(ph + 16);
                ah[t][3] = *(const uint32_t*)(ph + 8 * WPAD * 2 + 16);
            }
#pragma unroll
            for (int j = 0; j < 8; j++) {
                const int boff = ((wn * 64 + j * 8 + g) * WPAD + k0 + 2 * q) * 2;
                uint32_t bh[2];
                bh[0] = *(const uint32_t*)(smem + S_WHI + boff);
                bh[1] = *(const uint32_t*)(smem + S_WHI + boff + 16);
                mma16816(acc[0][j], ah[0], bh);
                mma16816(acc[1][j], ah[1], bh);
            }
        }

        // ---- epilogue: tanh + V-dot -> tile scores ----
        const float* sBias = (const float*)(smem + S_BIAS);
        const float* sV = (const float*)(smem + S_V);
        float p[4] = {0.f, 0.f, 0.f, 0.f};
#pragma unroll
        for (int t = 0; t < 2; t++) {
#pragma unroll
            for (int j = 0; j < 8; j++) {
                const int u0 = wn * 64 + j * 8 + 2 * q;
                const float bia0 = sBias[u0], bia1 = sBias[u0 + 1];
                const float v0 = sV[u0], v1 = sV[u0 + 1];
                p[t * 2 + 0] += tanh_ap(acc[t][j][0] + bia0) * v0
                              + tanh_ap(acc[t][j][1] + bia1) * v1;
                p[t * 2 + 1] += tanh_ap(acc[t][j][2] + bia0) * v0
                              + tanh_ap(acc[t][j][3] + bia1) * v1;
            }
        }
#pragma unroll
        for (int e = 0; e < 4; e++) {
            p[e] += __shfl_xor_sync(~0u, p[e], 1);
            p[e] += __shfl_xor_sync(~0u, p[e], 2);
        }
        if (q == 0) {
            float* part = (float*)(smem + S_PART);
            part[wn * 128 + wm * 32 + g]      = p[0];
            part[wn * 128 + wm * 32 + g + 8]  = p[1];
            part[wn * 128 + wm * 32 + g + 16] = p[2];
            part[wn * 128 + wm * 32 + g + 24] = p[3];
        }
        __syncthreads();
        float* sc = (float*)(smem + S_SC);
        if (tid < 128) {
            const float* part = (const float*)(smem + S_PART);
            sc[tid] = part[tid] + part[128 + tid];
        }
        __syncthreads();

        // ---- tile softmax stats ----
        float* red = (float*)(smem + S_RED);
        {
            float v = sc[tid & 127];
#pragma unroll
            for (int off = 16; off > 0; off >>= 1) v = fmaxf(v, __shfl_xor_sync(~0u, v, off));
            if (lane == 0) red[wid] = v;
        }
        __syncthreads();
        float M = fmaxf(fmaxf(red[0], red[1]), fmaxf(red[2], red[3]));
        M = fmaxf(M, fmaxf(fmaxf(red[4], red[5]), fmaxf(red[6], red[7])));
        __syncthreads();
        float e_val = 0.f;
        if (tid < 128) e_val = __expf(sc[tid] - M);
        {
            float v = e_val;
#pragma unroll
            for (int off = 16; off > 0; off >>= 1) v += __shfl_xor_sync(~0u, v, off);
            if (lane == 0) red[wid] = v;
        }
        if (tid < 128) sc[tid] = e_val;
        __syncthreads();
        const float S = red[0] + red[1] + red[2] + red[3];

        // ---- tile context from XH (fp16 RN image) ----
        {
            const int h = tid >> 6;          // 4 groups x 32 tokens
            const int pp = tid & 63;         // d-pair
            float2 cacc = make_float2(0.f, 0.f);
#pragma unroll 8
            for (int i = 0; i < 32; i++) {
                const int t = h * 32 + i;
                const float a = sc[t];
                float2 fh = __half22float2(
                    *(const __half2*)(smem + S_XH + (t * WPAD + 2 * pp) * 2));
                cacc.x = fmaf(a, fh.x, cacc.x);
                cacc.y = fmaf(a, fh.y, cacc.y);
            }
            ((float2*)(smem + S_CTX))[h * 64 + pp] = cacc;
        }
        __syncthreads();
        float* gout = g_tile + (size_t)tile * TSTRIDE;
        if (tid < 128) {
            const float* cp = (const float*)(smem + S_CTX);
            gout[tid] = cp[tid] + cp[128 + tid] + cp[256 + tid] + cp[384 + tid];
        }
        if (tid == 128) gout[128] = M;
        if (tid == 129) gout[129] = S;
        __syncthreads();
    }

    // ---- last CTA combines all tiles -> out ----
    __threadfence();
    if (tid == 0) {
        unsigned int old = atomicAdd(&g_done, 1u);
        ((int*)(smem + S_FLAG))[0] = (old == (unsigned int)(gridDim.x - 1));
    }
    __syncthreads();
    if (!((int*)(smem + S_FLAG))[0]) return;
    __threadfence();

    float* wgt = (float*)(smem + S_CMB);            // [64][16]
    float* invS = (float*)(smem + S_CMB + 4096);    // [64]
    if (tid < 64) {
        const float* tb = g_tile + (size_t)tid * NTILE * TSTRIDE;
        float M = -1e30f;
#pragma unroll
        for (int s = 0; s < NTILE; s++) M = fmaxf(M, tb[s * TSTRIDE + 128]);
        float S = 0.f;
#pragma unroll
        for (int s = 0; s < NTILE; s++) {
            float w = __expf(tb[s * TSTRIDE + 128] - M);
            wgt[tid * NTILE + s] = w;
            S = fmaf(tb[s * TSTRIDE + 129], w, S);
        }
        invS[tid] = 1.f / S;
    }
    __syncthreads();
#pragma unroll 4
    for (int iter = 0; iter < 32; iter++) {
        const int b = iter * 2 + (tid >> 7);
        const int d = tid & 127;
        const float* tb = g_tile + (size_t)b * NTILE * TSTRIDE;
        const float* wb = wgt + b * NTILE;
        float a = 0.f;
#pragma unroll
        for (int s = 0; s < NTILE; s++) a = fmaf(tb[s * TSTRIDE + d], wb[s], a);
        out[(size_t)b * DD + d] = a * invS[b];
    }
    if (tid == 0) g_done = 0;   // reset for next graph replay
}

// ---------------------------------------------------------------------------
extern "C" void kernel_launch(void* const* d_in, const int* in_sizes, int n_in,
                              void* d_out, int out_size) {
    const float* enc = (const float*)d_in[0];
    const float* W1w = (const float*)d_in[1];
    const float* W1b = (const float*)d_in[2];
    const float* W2w = (const float*)d_in[3];
    const float* W2b = (const float*)d_in[4];
    const float* Vw  = (const float*)d_in[5];
    // d_in[6] = V_b: softmax-invariant.
    float* out = (float*)d_out;

    cudaFuncSetAttribute(fused_kernel, cudaFuncAttributeMaxDynamicSharedMemorySize, S_TOTAL);
    fused_kernel<<<GRID, 256, S_TOTAL>>>(enc, W1w, W2w, W1b, W2b, Vw, out);
}